// round 1
// baseline (speedup 1.0000x reference)
#include <cuda_runtime.h>
#include <math.h>

// ---------------------------------------------------------------------------
// MultiHeadSelfAttention, B=2, S=2048, D=2048, H=16, HD=128 (fp32)
//
// Key simplification (derived from the reference's triu/transpose/softmax(-2)):
//   attn_i = ( sum_{j<i} v_j + exp(s_ii) * v_i ) / Z_i
//   Z_i    = i + sum_{r>=i} exp( (q_i . k_r) / sqrt(D) )
// So the attention-weight x V product is a prefix sum over V; only the
// triangular QK^T row sums and the diagonal are needed.
// ---------------------------------------------------------------------------

#define BB 2
#define SS 2048
#define DD 2048
#define HH 16
#define HDIM 128
#define NTOK (BB * SS)         // 4096
#define NCH 16                 // S / 128 chunks for the scan

// Scratch (static __device__ allocations; no cudaMalloc allowed)
__device__ float g_q[(size_t)NTOK * DD];
__device__ float g_k[(size_t)NTOK * DD];
__device__ float g_v[(size_t)NTOK * DD];
__device__ float g_attn[(size_t)NTOK * DD];
__device__ float g_Z[BB * HH * SS];
__device__ float g_E[BB * HH * SS];
__device__ float g_cs[BB * HH * NCH * HDIM];

// ---------------------------------------------------------------------------
// SGEMM (NT): C[n,m] = sum_k A[n,k] * W[m,k] + bias[m]
// A: [Nrows, D] row-major, W: [D, D] row-major, C: [Nrows, D].
// Tile 128x128x16, 256 threads, 8x8 per thread.
// ---------------------------------------------------------------------------
__global__ __launch_bounds__(256) void sgemm_nt_bias(
    const float* __restrict__ A, const float* __restrict__ W,
    const float* __restrict__ bias, float* __restrict__ C)
{
    __shared__ float As[16][128];
    __shared__ float Bs[16][128];

    const int tid = threadIdx.x;
    const int bm = blockIdx.y * 128;   // token rows
    const int bn = blockIdx.x * 128;   // output cols
    const int rowBase = (tid >> 4) * 8;
    const int colBase = (tid & 15) * 8;

    float acc[8][8];
#pragma unroll
    for (int i = 0; i < 8; i++)
#pragma unroll
        for (int j = 0; j < 8; j++) acc[i][j] = 0.0f;

    for (int k0 = 0; k0 < DD; k0 += 16) {
        // load A tile (128 rows x 16 k), transposed into As[k][row]
#pragma unroll
        for (int l = 0; l < 2; l++) {
            int f = tid + l * 256;            // 512 float4s
            int r = f >> 2;
            int kq = (f & 3) * 4;
            float4 v = *(const float4*)(A + (size_t)(bm + r) * DD + k0 + kq);
            As[kq + 0][r] = v.x; As[kq + 1][r] = v.y;
            As[kq + 2][r] = v.z; As[kq + 3][r] = v.w;
        }
        // load W tile (128 out-cols x 16 k) into Bs[k][col]
#pragma unroll
        for (int l = 0; l < 2; l++) {
            int f = tid + l * 256;
            int r = f >> 2;
            int kq = (f & 3) * 4;
            float4 v = *(const float4*)(W + (size_t)(bn + r) * DD + k0 + kq);
            Bs[kq + 0][r] = v.x; Bs[kq + 1][r] = v.y;
            Bs[kq + 2][r] = v.z; Bs[kq + 3][r] = v.w;
        }
        __syncthreads();

#pragma unroll
        for (int k = 0; k < 16; k++) {
            float a[8], b[8];
            *(float4*)&a[0] = *(const float4*)&As[k][rowBase];
            *(float4*)&a[4] = *(const float4*)&As[k][rowBase + 4];
            *(float4*)&b[0] = *(const float4*)&Bs[k][colBase];
            *(float4*)&b[4] = *(const float4*)&Bs[k][colBase + 4];
#pragma unroll
            for (int i = 0; i < 8; i++)
#pragma unroll
                for (int j = 0; j < 8; j++)
                    acc[i][j] += a[i] * b[j];
        }
        __syncthreads();
    }

    // epilogue: + bias, write out
#pragma unroll
    for (int i = 0; i < 8; i++) {
        int row = bm + rowBase + i;
#pragma unroll
        for (int j = 0; j < 8; j += 4) {
            float4 bv = *(const float4*)(bias + bn + colBase + j);
            float4 o;
            o.x = acc[i][j + 0] + bv.x;
            o.y = acc[i][j + 1] + bv.y;
            o.z = acc[i][j + 2] + bv.z;
            o.w = acc[i][j + 3] + bv.w;
            *(float4*)(C + (size_t)row * DD + bn + colBase + j) = o;
        }
    }
}

// ---------------------------------------------------------------------------
// Z kernel: for each (b,h,i): Z_i = i + sum_{r>=i} exp(q_i.k_r / sqrt(D)),
// E_i = exp(q_i.k_i / sqrt(D)). Tile: 64 i-rows per block, r chunks of 64,
// k chunks of 32. 256 threads; thread = (ti 0..15, tr 0..15), 4x4 micro-tile.
// ---------------------------------------------------------------------------
__global__ __launch_bounds__(256) void z_kernel(
    const float* __restrict__ Q, const float* __restrict__ K)
{
    __shared__ float Qs[HDIM][64];   // 32 KB, full head-dim of the Q tile
    __shared__ float Ks[32][64];     // 8 KB, one k-chunk of the K tile

    const int bh = blockIdx.y;
    const int b = bh >> 4;
    const int h = bh & 15;
    const int i0 = blockIdx.x * 64;
    const int tid = threadIdx.x;
    const float scale = 0.022097086912079612f;   // 1/sqrt(2048)

    // load Q tile: rows i0..i0+63, cols h*128..h*128+127  (64*128 floats)
    const float* Qbase = Q + ((size_t)b * SS + i0) * DD + h * HDIM;
    for (int f = tid; f < 64 * 32; f += 256) {   // 2048 float4s
        int r = f >> 5;
        int kq = (f & 31) * 4;
        float4 v = *(const float4*)(Qbase + (size_t)r * DD + kq);
        Qs[kq + 0][r] = v.x; Qs[kq + 1][r] = v.y;
        Qs[kq + 2][r] = v.z; Qs[kq + 3][r] = v.w;
    }
    __syncthreads();

    const int ti = tid >> 4, tr = tid & 15;
    const int ti4 = ti * 4, tr4 = tr * 4;
    float zacc[4] = {0.f, 0.f, 0.f, 0.f};
    const float* Kbh = K + (size_t)b * SS * DD + h * HDIM;

    for (int r0 = i0; r0 < SS; r0 += 64) {
        float s[4][4];
#pragma unroll
        for (int ii = 0; ii < 4; ii++)
#pragma unroll
            for (int rr = 0; rr < 4; rr++) s[ii][rr] = 0.0f;

        for (int kc = 0; kc < HDIM; kc += 32) {
            __syncthreads();
            for (int f = tid; f < 512; f += 256) {   // 64 rows * 8 f4
                int r = f >> 3;
                int kq = (f & 7) * 4;
                float4 v = *(const float4*)(Kbh + (size_t)(r0 + r) * DD + kc + kq);
                Ks[kq + 0][r] = v.x; Ks[kq + 1][r] = v.y;
                Ks[kq + 2][r] = v.z; Ks[kq + 3][r] = v.w;
            }
            __syncthreads();

#pragma unroll
            for (int kk = 0; kk < 32; kk++) {
                float4 qv = *(const float4*)&Qs[kc + kk][ti4];
                float4 kv = *(const float4*)&Ks[kk][tr4];
                s[0][0] += qv.x * kv.x; s[0][1] += qv.x * kv.y;
                s[0][2] += qv.x * kv.z; s[0][3] += qv.x * kv.w;
                s[1][0] += qv.y * kv.x; s[1][1] += qv.y * kv.y;
                s[1][2] += qv.y * kv.z; s[1][3] += qv.y * kv.w;
                s[2][0] += qv.z * kv.x; s[2][1] += qv.z * kv.y;
                s[2][2] += qv.z * kv.z; s[2][3] += qv.z * kv.w;
                s[3][0] += qv.w * kv.x; s[3][1] += qv.w * kv.y;
                s[3][2] += qv.w * kv.z; s[3][3] += qv.w * kv.w;
            }
        }

        // mask (r >= i), exp, accumulate
#pragma unroll
        for (int ii = 0; ii < 4; ii++) {
            int gi = i0 + ti4 + ii;
#pragma unroll
            for (int rr = 0; rr < 4; rr++) {
                int gr = r0 + tr4 + rr;
                if (gr >= gi) {
                    float e = __expf(s[ii][rr] * scale);
                    zacc[ii] += e;
                    if (gr == gi) g_E[(size_t)bh * SS + gi] = e;
                }
            }
        }
    }

    // reduce zacc over the 16 tr-lanes (contiguous tids -> width-16 shuffle)
#pragma unroll
    for (int off = 8; off > 0; off >>= 1) {
#pragma unroll
        for (int ii = 0; ii < 4; ii++)
            zacc[ii] += __shfl_down_sync(0xffffffffu, zacc[ii], off, 16);
    }
    if (tr == 0) {
#pragma unroll
        for (int ii = 0; ii < 4; ii++) {
            int gi = i0 + ti4 + ii;
            g_Z[(size_t)bh * SS + gi] = (float)gi + zacc[ii];
        }
    }
}

// ---------------------------------------------------------------------------
// Prefix-sum of V (3 passes), then apply: attn_i = (P_{i-1} + E_i*v_i)/Z_i
// attn is written in concat layout [B, S, H*HD] for the output projection.
// ---------------------------------------------------------------------------
__global__ void vchunk_kernel(const float* __restrict__ V)
{
    const int bh = blockIdx.x, ch = blockIdx.y, d = threadIdx.x;
    const int b = bh >> 4, h = bh & 15;
    const float* vp = V + ((size_t)b * SS + ch * 128) * DD + h * HDIM + d;
    float sum = 0.0f;
#pragma unroll 8
    for (int i = 0; i < 128; i++) sum += vp[(size_t)i * DD];
    g_cs[((size_t)bh * NCH + ch) * HDIM + d] = sum;
}

__global__ void vprefix_kernel()
{
    const int bh = blockIdx.x, d = threadIdx.x;
    float run = 0.0f;
    for (int ch = 0; ch < NCH; ch++) {
        size_t idx = ((size_t)bh * NCH + ch) * HDIM + d;
        float t = g_cs[idx];
        g_cs[idx] = run;     // exclusive prefix of chunk sums
        run += t;
    }
}

__global__ void scan_apply_kernel(const float* __restrict__ V,
                                  float* __restrict__ Aout)
{
    const int bh = blockIdx.x, ch = blockIdx.y, d = threadIdx.x;
    const int b = bh >> 4, h = bh & 15;
    float run = g_cs[((size_t)bh * NCH + ch) * HDIM + d];
    const float* vp = V + ((size_t)b * SS + ch * 128) * DD + h * HDIM + d;
    float* ap = Aout + ((size_t)b * SS + ch * 128) * DD + h * HDIM + d;
    const float* Ep = g_E + (size_t)bh * SS + ch * 128;
    const float* Zp = g_Z + (size_t)bh * SS + ch * 128;
#pragma unroll 4
    for (int i = 0; i < 128; i++) {
        float vv = vp[(size_t)i * DD];
        float rcp = __fdividef(1.0f, Zp[i]);
        ap[(size_t)i * DD] = (run + Ep[i] * vv) * rcp;
        run += vv;
    }
}

// ---------------------------------------------------------------------------
// Launch
// ---------------------------------------------------------------------------
extern "C" void kernel_launch(void* const* d_in, const int* in_sizes, int n_in,
                              void* d_out, int out_size)
{
    const float* x   = (const float*)d_in[0];
    const float* wq  = (const float*)d_in[1];
    const float* bq  = (const float*)d_in[2];
    const float* wk  = (const float*)d_in[3];
    const float* bk  = (const float*)d_in[4];
    const float* wv  = (const float*)d_in[5];
    const float* bv  = (const float*)d_in[6];
    const float* wo  = (const float*)d_in[7];
    const float* bo  = (const float*)d_in[8];
    float* out = (float*)d_out;

    void *pq, *pk, *pv, *pa;
    cudaGetSymbolAddress(&pq, g_q);
    cudaGetSymbolAddress(&pk, g_k);
    cudaGetSymbolAddress(&pv, g_v);
    cudaGetSymbolAddress(&pa, g_attn);
    float* q = (float*)pq;
    float* k = (float*)pk;
    float* v = (float*)pv;
    float* attn = (float*)pa;

    dim3 gGemm(DD / 128, NTOK / 128);   // (16, 32)
    sgemm_nt_bias<<<gGemm, 256>>>(x, wq, bq, q);
    sgemm_nt_bias<<<gGemm, 256>>>(x, wk, bk, k);
    sgemm_nt_bias<<<gGemm, 256>>>(x, wv, bv, v);

    dim3 gZ(SS / 64, BB * HH);          // (32, 32)
    z_kernel<<<gZ, 256>>>(q, k);

    dim3 gScan(BB * HH, NCH);           // (32, 16)
    vchunk_kernel<<<gScan, HDIM>>>(v);
    vprefix_kernel<<<BB * HH, HDIM>>>();
    scan_apply_kernel<<<gScan, HDIM>>>(v, attn);

    sgemm_nt_bias<<<gGemm, 256>>>(attn, wo, bo, out);
}

// round 5
// speedup vs baseline: 2.3594x; 2.3594x over previous
#include <cuda_runtime.h>
#include <cuda_bf16.h>
#include <math.h>
#include <stdint.h>

// ---------------------------------------------------------------------------
// MultiHeadSelfAttention, B=2, S=2048, D=2048, H=16, HD=128
//
//   attn_i = ( sum_{j<i} v_j + exp(s_ii) * v_i ) / Z_i
//   Z_i    = i + sum_{r>=i} exp( (q_i . k_r) / sqrt(D) )
//
// Round 3: harness PTX target is compute_103 (no 'a' features!), so no
// tcgen05/TMA. GEMMs use mma.sync.m16n8k16 bf16 (HMMA) with cp.async
// double buffering. Q,K: single bf16 product (score noise washes out in
// exp/sum). V, O-proj: 3-way bf16 split (hi*hi + hi*lo + lo*hi, fp32 accum).
// ---------------------------------------------------------------------------

#define BB 2
#define SS 2048
#define DD 2048
#define HH 16
#define HDIM 128
#define NTOK (BB * SS)         // 4096
#define NCH 16
#define RSTRIDE 80             // smem row stride in bytes (64B data + 16B pad)

// fp32 scratch
__device__ float g_q[(size_t)NTOK * DD];
__device__ float g_k[(size_t)NTOK * DD];
__device__ float g_v[(size_t)NTOK * DD];
__device__ float g_attn[(size_t)NTOK * DD];
__device__ float g_Z[BB * HH * SS];
__device__ float g_E[BB * HH * SS];
__device__ float g_cs[BB * HH * NCH * HDIM];

// bf16 scratch
__device__ __nv_bfloat16 g_xh[(size_t)NTOK * DD];
__device__ __nv_bfloat16 g_xl[(size_t)NTOK * DD];
__device__ __nv_bfloat16 g_ah[(size_t)NTOK * DD];
__device__ __nv_bfloat16 g_al[(size_t)NTOK * DD];
__device__ __nv_bfloat16 g_wqh[(size_t)DD * DD];
__device__ __nv_bfloat16 g_wkh[(size_t)DD * DD];
__device__ __nv_bfloat16 g_wvh[(size_t)DD * DD];
__device__ __nv_bfloat16 g_wvl[(size_t)DD * DD];
__device__ __nv_bfloat16 g_woh[(size_t)DD * DD];
__device__ __nv_bfloat16 g_wol[(size_t)DD * DD];

// ---------------------------------------------------------------------------
// Helpers (base compute_103 ISA only)
// ---------------------------------------------------------------------------
__device__ __forceinline__ uint32_t smem_u32(const void* p) {
    return (uint32_t)__cvta_generic_to_shared(p);
}

__device__ __forceinline__ void cp16(uint32_t dst, const void* src) {
    asm volatile("cp.async.cg.shared.global [%0], [%1], 16;" :: "r"(dst), "l"(src));
}

__device__ __forceinline__ void ldsm4(uint32_t& r0, uint32_t& r1, uint32_t& r2,
                                      uint32_t& r3, uint32_t addr) {
    asm volatile("ldmatrix.sync.aligned.m8n8.x4.shared.b16 {%0,%1,%2,%3}, [%4];"
                 : "=r"(r0), "=r"(r1), "=r"(r2), "=r"(r3) : "r"(addr));
}

__device__ __forceinline__ void mma_bf16(float* c, const uint32_t* a,
                                         uint32_t b0, uint32_t b1) {
    asm volatile("mma.sync.aligned.m16n8k16.row.col.f32.bf16.bf16.f32 "
                 "{%0,%1,%2,%3}, {%4,%5,%6,%7}, {%8,%9}, {%0,%1,%2,%3};"
                 : "+f"(c[0]), "+f"(c[1]), "+f"(c[2]), "+f"(c[3])
                 : "r"(a[0]), "r"(a[1]), "r"(a[2]), "r"(a[3]), "r"(b0), "r"(b1));
}

// ---------------------------------------------------------------------------
// fp32 -> bf16 conversions
// ---------------------------------------------------------------------------
__global__ __launch_bounds__(256) void split_kernel(
    const float* __restrict__ in, __nv_bfloat16* __restrict__ hi,
    __nv_bfloat16* __restrict__ lo, int n)
{
    int i = (blockIdx.x * 256 + threadIdx.x) * 4;
    if (i >= n) return;
    float4 v = *(const float4*)(in + i);
    __nv_bfloat16 h0 = __float2bfloat16(v.x);
    __nv_bfloat16 h1 = __float2bfloat16(v.y);
    __nv_bfloat16 h2 = __float2bfloat16(v.z);
    __nv_bfloat16 h3 = __float2bfloat16(v.w);
    __nv_bfloat16 l0 = __float2bfloat16(v.x - __bfloat162float(h0));
    __nv_bfloat16 l1 = __float2bfloat16(v.y - __bfloat162float(h1));
    __nv_bfloat16 l2 = __float2bfloat16(v.z - __bfloat162float(h2));
    __nv_bfloat16 l3 = __float2bfloat16(v.w - __bfloat162float(h3));
    __nv_bfloat162* hp = reinterpret_cast<__nv_bfloat162*>(hi + i);
    __nv_bfloat162* lp = reinterpret_cast<__nv_bfloat162*>(lo + i);
    hp[0] = __nv_bfloat162(h0, h1);
    hp[1] = __nv_bfloat162(h2, h3);
    lp[0] = __nv_bfloat162(l0, l1);
    lp[1] = __nv_bfloat162(l2, l3);
}

__global__ __launch_bounds__(256) void tobf16_kernel(
    const float* __restrict__ in, __nv_bfloat16* __restrict__ out, int n)
{
    int i = (blockIdx.x * 256 + threadIdx.x) * 4;
    if (i >= n) return;
    float4 v = *(const float4*)(in + i);
    __nv_bfloat162* op = reinterpret_cast<__nv_bfloat162*>(out + i);
    op[0] = __nv_bfloat162(__float2bfloat16(v.x), __float2bfloat16(v.y));
    op[1] = __nv_bfloat162(__float2bfloat16(v.z), __float2bfloat16(v.w));
}

// ---------------------------------------------------------------------------
// bf16 mma.sync GEMM: C[m,n] = sum_p sum_k Ap[m,k]*Bp[n,k]  (+ bias[n])
// Tile 128x128, BK=32, 256 threads (8 warps as 4x2), warp tile 32x64.
// Double-buffered cp.async. smem rows padded to 80B -> conflict-free ldmatrix.
// ---------------------------------------------------------------------------
__device__ __forceinline__ void gemm_load_chunk(
    const __nv_bfloat16* __restrict__ A, const __nv_bfloat16* __restrict__ B,
    int bm, int bn, int k0, unsigned char* sA, unsigned char* sB, int tid)
{
#pragma unroll
    for (int l = 0; l < 2; l++) {
        int i = tid + l * 256;          // 512 x 16B per tile
        int r = i >> 2;
        int seg = i & 3;
        cp16(smem_u32(sA + r * RSTRIDE + seg * 16),
             A + (size_t)(bm + r) * DD + k0 + seg * 8);
        cp16(smem_u32(sB + r * RSTRIDE + seg * 16),
             B + (size_t)(bn + r) * DD + k0 + seg * 8);
    }
    asm volatile("cp.async.commit_group;" ::: "memory");
}

__global__ __launch_bounds__(256) void gemm_mma(
    const __nv_bfloat16* __restrict__ A0, const __nv_bfloat16* __restrict__ B0,
    const __nv_bfloat16* __restrict__ A1, const __nv_bfloat16* __restrict__ B1,
    const __nv_bfloat16* __restrict__ A2, const __nv_bfloat16* __restrict__ B2,
    int nprod, const float* __restrict__ bias, float* __restrict__ C)
{
    __shared__ __align__(16) unsigned char sm[2][2][128 * RSTRIDE];  // 40KB

    const int tid = threadIdx.x;
    const int lid = tid & 31;
    const int wid = tid >> 5;
    const int wm = wid >> 1;          // 0..3
    const int wn = wid & 1;           // 0..1
    const int bn = blockIdx.x * 128;
    const int bm = blockIdx.y * 128;

    const __nv_bfloat16* Ap[3] = {A0, A1, A2};
    const __nv_bfloat16* Bp[3] = {B0, B1, B2};
    const int nch = nprod << 6;       // 64 chunks of BK=32 per product

    float acc[2][8][4];
#pragma unroll
    for (int i = 0; i < 2; i++)
#pragma unroll
        for (int j = 0; j < 8; j++)
#pragma unroll
            for (int q = 0; q < 4; q++) acc[i][j][q] = 0.0f;

    // ldmatrix lane addressing: 4 groups of 8 lanes ->
    //   (rows 0-7,k0),(rows 8-15,k0),(rows 0-7,k+16B),(rows 8-15,k+16B)
    const int rowsel = (lid & 7) + ((lid >> 3) & 1) * 8;
    const int kbsel = (lid >> 4) * 16;

    gemm_load_chunk(Ap[0], Bp[0], bm, bn, 0, sm[0][0], sm[0][1], tid);

    for (int c = 0; c < nch; c++) {
        if (c + 1 < nch) {
            int p = (c + 1) >> 6;
            gemm_load_chunk(Ap[p], Bp[p], bm, bn, ((c + 1) & 63) << 5,
                            sm[(c + 1) & 1][0], sm[(c + 1) & 1][1], tid);
            asm volatile("cp.async.wait_group 1;" ::: "memory");
        } else {
            asm volatile("cp.async.wait_group 0;" ::: "memory");
        }
        __syncthreads();

        const int buf = c & 1;
        uint32_t aAddr = smem_u32(&sm[buf][0][0]) + (wm * 32 + rowsel) * RSTRIDE + kbsel;
        uint32_t bAddr = smem_u32(&sm[buf][1][0]) + (wn * 64 + rowsel) * RSTRIDE + kbsel;

#pragma unroll
        for (int ks = 0; ks < 2; ks++) {
            uint32_t a[2][4];
            ldsm4(a[0][0], a[0][1], a[0][2], a[0][3], aAddr + ks * 32);
            ldsm4(a[1][0], a[1][1], a[1][2], a[1][3], aAddr + 16 * RSTRIDE + ks * 32);
#pragma unroll
            for (int ng = 0; ng < 4; ng++) {
                uint32_t r0, r1, r2, r3;
                ldsm4(r0, r1, r2, r3, bAddr + ng * 16 * RSTRIDE + ks * 32);
                mma_bf16(acc[0][2 * ng + 0], a[0], r0, r2);
                mma_bf16(acc[0][2 * ng + 1], a[0], r1, r3);
                mma_bf16(acc[1][2 * ng + 0], a[1], r0, r2);
                mma_bf16(acc[1][2 * ng + 1], a[1], r1, r3);
            }
        }
        __syncthreads();
    }

    // epilogue: c-frag (row = lid/4 [+8], col = 2*(lid%4)) + bias
    const int trow = lid >> 2;
    const int tcol = (lid & 3) * 2;
#pragma unroll
    for (int mt = 0; mt < 2; mt++) {
        int r0 = bm + wm * 32 + mt * 16 + trow;
#pragma unroll
        for (int nt = 0; nt < 8; nt++) {
            int cc = bn + wn * 64 + nt * 8 + tcol;
            float2 bv = *(const float2*)(bias + cc);
            float2 o0, o1;
            o0.x = acc[mt][nt][0] + bv.x;
            o0.y = acc[mt][nt][1] + bv.y;
            o1.x = acc[mt][nt][2] + bv.x;
            o1.y = acc[mt][nt][3] + bv.y;
            *(float2*)(C + (size_t)r0 * DD + cc) = o0;
            *(float2*)(C + (size_t)(r0 + 8) * DD + cc) = o1;
        }
    }
}

// ---------------------------------------------------------------------------
// Z kernel: Z_i = i + sum_{r>=i} exp(q_i.k_r/sqrt(D)), E_i = diag exp.
// ---------------------------------------------------------------------------
__global__ __launch_bounds__(256) void z_kernel(
    const float* __restrict__ Q, const float* __restrict__ K)
{
    __shared__ float Qs[HDIM][64];
    __shared__ float Ks[32][64];

    const int bh = blockIdx.y;
    const int b = bh >> 4;
    const int h = bh & 15;
    const int i0 = blockIdx.x * 64;
    const int tid = threadIdx.x;
    const float scale = 0.022097086912079612f;   // 1/sqrt(2048)

    const float* Qbase = Q + ((size_t)b * SS + i0) * DD + h * HDIM;
    for (int f = tid; f < 64 * 32; f += 256) {
        int r = f >> 5;
        int kq = (f & 31) * 4;
        float4 v = *(const float4*)(Qbase + (size_t)r * DD + kq);
        Qs[kq + 0][r] = v.x; Qs[kq + 1][r] = v.y;
        Qs[kq + 2][r] = v.z; Qs[kq + 3][r] = v.w;
    }
    __syncthreads();

    const int ti = tid >> 4, tr = tid & 15;
    const int ti4 = ti * 4, tr4 = tr * 4;
    float zacc[4] = {0.f, 0.f, 0.f, 0.f};
    const float* Kbh = K + (size_t)b * SS * DD + h * HDIM;

    for (int r0 = i0; r0 < SS; r0 += 64) {
        float s[4][4];
#pragma unroll
        for (int ii = 0; ii < 4; ii++)
#pragma unroll
            for (int rr = 0; rr < 4; rr++) s[ii][rr] = 0.0f;

        for (int kc = 0; kc < HDIM; kc += 32) {
            __syncthreads();
            for (int f = tid; f < 512; f += 256) {
                int r = f >> 3;
                int kq = (f & 7) * 4;
                float4 v = *(const float4*)(Kbh + (size_t)(r0 + r) * DD + kc + kq);
                Ks[kq + 0][r] = v.x; Ks[kq + 1][r] = v.y;
                Ks[kq + 2][r] = v.z; Ks[kq + 3][r] = v.w;
            }
            __syncthreads();

#pragma unroll
            for (int kk = 0; kk < 32; kk++) {
                float4 qv = *(const float4*)&Qs[kc + kk][ti4];
                float4 kv = *(const float4*)&Ks[kk][tr4];
                s[0][0] += qv.x * kv.x; s[0][1] += qv.x * kv.y;
                s[0][2] += qv.x * kv.z; s[0][3] += qv.x * kv.w;
                s[1][0] += qv.y * kv.x; s[1][1] += qv.y * kv.y;
                s[1][2] += qv.y * kv.z; s[1][3] += qv.y * kv.w;
                s[2][0] += qv.z * kv.x; s[2][1] += qv.z * kv.y;
                s[2][2] += qv.z * kv.z; s[2][3] += qv.z * kv.w;
                s[3][0] += qv.w * kv.x; s[3][1] += qv.w * kv.y;
                s[3][2] += qv.w * kv.z; s[3][3] += qv.w * kv.w;
            }
        }

#pragma unroll
        for (int ii = 0; ii < 4; ii++) {
            int gi = i0 + ti4 + ii;
#pragma unroll
            for (int rr = 0; rr < 4; rr++) {
                int gr = r0 + tr4 + rr;
                if (gr >= gi) {
                    float e = __expf(s[ii][rr] * scale);
                    zacc[ii] += e;
                    if (gr == gi) g_E[(size_t)bh * SS + gi] = e;
                }
            }
        }
    }

#pragma unroll
    for (int off = 8; off > 0; off >>= 1) {
#pragma unroll
        for (int ii = 0; ii < 4; ii++)
            zacc[ii] += __shfl_down_sync(0xffffffffu, zacc[ii], off, 16);
    }
    if (tr == 0) {
#pragma unroll
        for (int ii = 0; ii < 4; ii++) {
            int gi = i0 + ti4 + ii;
            g_Z[(size_t)bh * SS + gi] = (float)gi + zacc[ii];
        }
    }
}

// ---------------------------------------------------------------------------
// Prefix-sum of V + apply
// ---------------------------------------------------------------------------
__global__ void vchunk_kernel(const float* __restrict__ V)
{
    const int bh = blockIdx.x, ch = blockIdx.y, d = threadIdx.x;
    const int b = bh >> 4, h = bh & 15;
    const float* vp = V + ((size_t)b * SS + ch * 128) * DD + h * HDIM + d;
    float sum = 0.0f;
#pragma unroll 8
    for (int i = 0; i < 128; i++) sum += vp[(size_t)i * DD];
    g_cs[((size_t)bh * NCH + ch) * HDIM + d] = sum;
}

__global__ void vprefix_kernel()
{
    const int bh = blockIdx.x, d = threadIdx.x;
    float run = 0.0f;
    for (int ch = 0; ch < NCH; ch++) {
        size_t idx = ((size_t)bh * NCH + ch) * HDIM + d;
        float t = g_cs[idx];
        g_cs[idx] = run;
        run += t;
    }
}

__global__ void scan_apply_kernel(const float* __restrict__ V,
                                  float* __restrict__ Aout)
{
    const int bh = blockIdx.x, ch = blockIdx.y, d = threadIdx.x;
    const int b = bh >> 4, h = bh & 15;
    float run = g_cs[((size_t)bh * NCH + ch) * HDIM + d];
    const float* vp = V + ((size_t)b * SS + ch * 128) * DD + h * HDIM + d;
    float* ap = Aout + ((size_t)b * SS + ch * 128) * DD + h * HDIM + d;
    const float* Ep = g_E + (size_t)bh * SS + ch * 128;
    const float* Zp = g_Z + (size_t)bh * SS + ch * 128;
#pragma unroll 4
    for (int i = 0; i < 128; i++) {
        float vv = vp[(size_t)i * DD];
        float rcp = __fdividef(1.0f, Zp[i]);
        ap[(size_t)i * DD] = (run + Ep[i] * vv) * rcp;
        run += vv;
    }
}

// ---------------------------------------------------------------------------
// Launch
// ---------------------------------------------------------------------------
extern "C" void kernel_launch(void* const* d_in, const int* in_sizes, int n_in,
                              void* d_out, int out_size)
{
    const float* x   = (const float*)d_in[0];
    const float* wq  = (const float*)d_in[1];
    const float* bq  = (const float*)d_in[2];
    const float* wk  = (const float*)d_in[3];
    const float* bk  = (const float*)d_in[4];
    const float* wv  = (const float*)d_in[5];
    const float* bv  = (const float*)d_in[6];
    const float* wo  = (const float*)d_in[7];
    const float* bo  = (const float*)d_in[8];
    float* out = (float*)d_out;

    void *pq, *pk, *pv, *pa;
    cudaGetSymbolAddress(&pq, g_q);
    cudaGetSymbolAddress(&pk, g_k);
    cudaGetSymbolAddress(&pv, g_v);
    cudaGetSymbolAddress(&pa, g_attn);
    float* q = (float*)pq;
    float* k = (float*)pk;
    float* v = (float*)pv;
    float* attn = (float*)pa;

    void *pxh, *pxl, *pah, *pal, *pwqh, *pwkh, *pwvh, *pwvl, *pwoh, *pwol;
    cudaGetSymbolAddress(&pxh, g_xh);   cudaGetSymbolAddress(&pxl, g_xl);
    cudaGetSymbolAddress(&pah, g_ah);   cudaGetSymbolAddress(&pal, g_al);
    cudaGetSymbolAddress(&pwqh, g_wqh); cudaGetSymbolAddress(&pwkh, g_wkh);
    cudaGetSymbolAddress(&pwvh, g_wvh); cudaGetSymbolAddress(&pwvl, g_wvl);
    cudaGetSymbolAddress(&pwoh, g_woh); cudaGetSymbolAddress(&pwol, g_wol);

    __nv_bfloat16* xh = (__nv_bfloat16*)pxh;
    __nv_bfloat16* xl = (__nv_bfloat16*)pxl;
    __nv_bfloat16* ah = (__nv_bfloat16*)pah;
    __nv_bfloat16* al = (__nv_bfloat16*)pal;
    __nv_bfloat16* wqh = (__nv_bfloat16*)pwqh;
    __nv_bfloat16* wkh = (__nv_bfloat16*)pwkh;
    __nv_bfloat16* wvh = (__nv_bfloat16*)pwvh;
    __nv_bfloat16* wvl = (__nv_bfloat16*)pwvl;
    __nv_bfloat16* woh = (__nv_bfloat16*)pwoh;
    __nv_bfloat16* wol = (__nv_bfloat16*)pwol;

    const int nTok = NTOK * DD;   // 8.4M
    const int nW   = DD * DD;     // 4.2M

    split_kernel<<<nTok / 1024, 256>>>(x, xh, xl, nTok);
    tobf16_kernel<<<nW / 1024, 256>>>(wq, wqh, nW);
    tobf16_kernel<<<nW / 1024, 256>>>(wk, wkh, nW);
    split_kernel<<<nW / 1024, 256>>>(wv, wvh, wvl, nW);
    split_kernel<<<nW / 1024, 256>>>(wo, woh, wol, nW);

    dim3 gGemm(DD / 128, NTOK / 128);   // (16, 32)
    // Q, K: single bf16 product
    gemm_mma<<<gGemm, 256>>>(xh, wqh, xh, wqh, xh, wqh, 1, bq, q);
    gemm_mma<<<gGemm, 256>>>(xh, wkh, xh, wkh, xh, wkh, 1, bk, k);
    // V: 3-way split
    gemm_mma<<<gGemm, 256>>>(xh, wvh, xh, wvl, xl, wvh, 3, bv, v);

    dim3 gZ(SS / 64, BB * HH);
    z_kernel<<<gZ, 256>>>(q, k);

    dim3 gScan(BB * HH, NCH);
    vchunk_kernel<<<gScan, HDIM>>>(v);
    vprefix_kernel<<<BB * HH, HDIM>>>();
    scan_apply_kernel<<<gScan, HDIM>>>(v, attn);

    split_kernel<<<nTok / 1024, 256>>>(attn, ah, al, nTok);
    // O-projection: 3-way split
    gemm_mma<<<gGemm, 256>>>(ah, woh, ah, wol, al, woh, 3, bo, out);
}

// round 6
// speedup vs baseline: 3.4994x; 1.4832x over previous
#include <cuda_runtime.h>
#include <cuda_bf16.h>
#include <math.h>
#include <stdint.h>

// ---------------------------------------------------------------------------
// MultiHeadSelfAttention, B=2, S=2048, D=2048, H=16, HD=128
//
//   attn_i = ( sum_{j<i} v_j + exp(s_ii) * v_i ) / Z_i
//   Z_i    = i + sum_{r>=i} exp( (q_i . k_r) / sqrt(D) )
//
// Round 5: Z row-sums move to mma.sync (bf16 HMMA). Q/K projections emit
// bf16 directly; V/O-proj stay 3-way-split bf16 for fp32-grade accuracy.
// ---------------------------------------------------------------------------

#define BB 2
#define SS 2048
#define DD 2048
#define HH 16
#define HDIM 128
#define NTOK (BB * SS)         // 4096
#define NCH 16
#define RSTRIDE 80             // gemm smem row stride (64B data + 16B pad)
#define ZRS 272                // z smem row stride (256B data + 16B pad)

// fp32 scratch
__device__ float g_v[(size_t)NTOK * DD];
__device__ float g_Z[BB * HH * SS];
__device__ float g_E[BB * HH * SS];
__device__ float g_cs[BB * HH * NCH * HDIM];

// bf16 scratch
__device__ __nv_bfloat16 g_xh[(size_t)NTOK * DD];
__device__ __nv_bfloat16 g_xl[(size_t)NTOK * DD];
__device__ __nv_bfloat16 g_qb[(size_t)NTOK * DD];
__device__ __nv_bfloat16 g_kb[(size_t)NTOK * DD];
__device__ __nv_bfloat16 g_ah[(size_t)NTOK * DD];
__device__ __nv_bfloat16 g_al[(size_t)NTOK * DD];
__device__ __nv_bfloat16 g_wqh[(size_t)DD * DD];
__device__ __nv_bfloat16 g_wkh[(size_t)DD * DD];
__device__ __nv_bfloat16 g_wvh[(size_t)DD * DD];
__device__ __nv_bfloat16 g_wvl[(size_t)DD * DD];
__device__ __nv_bfloat16 g_woh[(size_t)DD * DD];
__device__ __nv_bfloat16 g_wol[(size_t)DD * DD];

// ---------------------------------------------------------------------------
// Helpers (base compute_103 ISA only)
// ---------------------------------------------------------------------------
__device__ __forceinline__ uint32_t smem_u32(const void* p) {
    return (uint32_t)__cvta_generic_to_shared(p);
}

__device__ __forceinline__ void cp16(uint32_t dst, const void* src) {
    asm volatile("cp.async.cg.shared.global [%0], [%1], 16;" :: "r"(dst), "l"(src));
}

__device__ __forceinline__ void ldsm4(uint32_t& r0, uint32_t& r1, uint32_t& r2,
                                      uint32_t& r3, uint32_t addr) {
    asm volatile("ldmatrix.sync.aligned.m8n8.x4.shared.b16 {%0,%1,%2,%3}, [%4];"
                 : "=r"(r0), "=r"(r1), "=r"(r2), "=r"(r3) : "r"(addr));
}

__device__ __forceinline__ void mma_bf16(float* c, const uint32_t* a,
                                         uint32_t b0, uint32_t b1) {
    asm volatile("mma.sync.aligned.m16n8k16.row.col.f32.bf16.bf16.f32 "
                 "{%0,%1,%2,%3}, {%4,%5,%6,%7}, {%8,%9}, {%0,%1,%2,%3};"
                 : "+f"(c[0]), "+f"(c[1]), "+f"(c[2]), "+f"(c[3])
                 : "r"(a[0]), "r"(a[1]), "r"(a[2]), "r"(a[3]), "r"(b0), "r"(b1));
}

// ---------------------------------------------------------------------------
// fp32 -> bf16 conversions
// ---------------------------------------------------------------------------
__global__ __launch_bounds__(256) void split_kernel(
    const float* __restrict__ in, __nv_bfloat16* __restrict__ hi,
    __nv_bfloat16* __restrict__ lo, int n)
{
    int i = (blockIdx.x * 256 + threadIdx.x) * 4;
    if (i >= n) return;
    float4 v = *(const float4*)(in + i);
    __nv_bfloat16 h0 = __float2bfloat16(v.x);
    __nv_bfloat16 h1 = __float2bfloat16(v.y);
    __nv_bfloat16 h2 = __float2bfloat16(v.z);
    __nv_bfloat16 h3 = __float2bfloat16(v.w);
    __nv_bfloat16 l0 = __float2bfloat16(v.x - __bfloat162float(h0));
    __nv_bfloat16 l1 = __float2bfloat16(v.y - __bfloat162float(h1));
    __nv_bfloat16 l2 = __float2bfloat16(v.z - __bfloat162float(h2));
    __nv_bfloat16 l3 = __float2bfloat16(v.w - __bfloat162float(h3));
    __nv_bfloat162* hp = reinterpret_cast<__nv_bfloat162*>(hi + i);
    __nv_bfloat162* lp = reinterpret_cast<__nv_bfloat162*>(lo + i);
    hp[0] = __nv_bfloat162(h0, h1);
    hp[1] = __nv_bfloat162(h2, h3);
    lp[0] = __nv_bfloat162(l0, l1);
    lp[1] = __nv_bfloat162(l2, l3);
}

__global__ __launch_bounds__(256) void tobf16_kernel(
    const float* __restrict__ in, __nv_bfloat16* __restrict__ out, int n)
{
    int i = (blockIdx.x * 256 + threadIdx.x) * 4;
    if (i >= n) return;
    float4 v = *(const float4*)(in + i);
    __nv_bfloat162* op = reinterpret_cast<__nv_bfloat162*>(out + i);
    op[0] = __nv_bfloat162(__float2bfloat16(v.x), __float2bfloat16(v.y));
    op[1] = __nv_bfloat162(__float2bfloat16(v.z), __float2bfloat16(v.w));
}

// ---------------------------------------------------------------------------
// bf16 mma.sync GEMM: C[m,n] = sum_p sum_k Ap[m,k]*Bp[n,k]  (+ bias[n])
// Tile 128x128, BK=32, 256 threads (8 warps as 4x2), warp tile 32x64.
// Optional fp32 output C and/or bf16 output Cb.
// ---------------------------------------------------------------------------
__device__ __forceinline__ void gemm_load_chunk(
    const __nv_bfloat16* __restrict__ A, const __nv_bfloat16* __restrict__ B,
    int bm, int bn, int k0, unsigned char* sA, unsigned char* sB, int tid)
{
#pragma unroll
    for (int l = 0; l < 2; l++) {
        int i = tid + l * 256;          // 512 x 16B per tile
        int r = i >> 2;
        int seg = i & 3;
        cp16(smem_u32(sA + r * RSTRIDE + seg * 16),
             A + (size_t)(bm + r) * DD + k0 + seg * 8);
        cp16(smem_u32(sB + r * RSTRIDE + seg * 16),
             B + (size_t)(bn + r) * DD + k0 + seg * 8);
    }
    asm volatile("cp.async.commit_group;" ::: "memory");
}

__global__ __launch_bounds__(256) void gemm_mma(
    const __nv_bfloat16* __restrict__ A0, const __nv_bfloat16* __restrict__ B0,
    const __nv_bfloat16* __restrict__ A1, const __nv_bfloat16* __restrict__ B1,
    const __nv_bfloat16* __restrict__ A2, const __nv_bfloat16* __restrict__ B2,
    int nprod, const float* __restrict__ bias, float* __restrict__ C,
    __nv_bfloat16* __restrict__ Cb)
{
    __shared__ __align__(16) unsigned char sm[2][2][128 * RSTRIDE];  // 40KB

    const int tid = threadIdx.x;
    const int lid = tid & 31;
    const int wid = tid >> 5;
    const int wm = wid >> 1;          // 0..3
    const int wn = wid & 1;           // 0..1
    const int bn = blockIdx.x * 128;
    const int bm = blockIdx.y * 128;

    const __nv_bfloat16* Ap[3] = {A0, A1, A2};
    const __nv_bfloat16* Bp[3] = {B0, B1, B2};
    const int nch = nprod << 6;       // 64 chunks of BK=32 per product

    float acc[2][8][4];
#pragma unroll
    for (int i = 0; i < 2; i++)
#pragma unroll
        for (int j = 0; j < 8; j++)
#pragma unroll
            for (int q = 0; q < 4; q++) acc[i][j][q] = 0.0f;

    const int rowsel = (lid & 7) + ((lid >> 3) & 1) * 8;
    const int kbsel = (lid >> 4) * 16;

    gemm_load_chunk(Ap[0], Bp[0], bm, bn, 0, sm[0][0], sm[0][1], tid);

    for (int c = 0; c < nch; c++) {
        if (c + 1 < nch) {
            int p = (c + 1) >> 6;
            gemm_load_chunk(Ap[p], Bp[p], bm, bn, ((c + 1) & 63) << 5,
                            sm[(c + 1) & 1][0], sm[(c + 1) & 1][1], tid);
            asm volatile("cp.async.wait_group 1;" ::: "memory");
        } else {
            asm volatile("cp.async.wait_group 0;" ::: "memory");
        }
        __syncthreads();

        const int buf = c & 1;
        uint32_t aAddr = smem_u32(&sm[buf][0][0]) + (wm * 32 + rowsel) * RSTRIDE + kbsel;
        uint32_t bAddr = smem_u32(&sm[buf][1][0]) + (wn * 64 + rowsel) * RSTRIDE + kbsel;

#pragma unroll
        for (int ks = 0; ks < 2; ks++) {
            uint32_t a[2][4];
            ldsm4(a[0][0], a[0][1], a[0][2], a[0][3], aAddr + ks * 32);
            ldsm4(a[1][0], a[1][1], a[1][2], a[1][3], aAddr + 16 * RSTRIDE + ks * 32);
#pragma unroll
            for (int ng = 0; ng < 4; ng++) {
                uint32_t r0, r1, r2, r3;
                ldsm4(r0, r1, r2, r3, bAddr + ng * 16 * RSTRIDE + ks * 32);
                mma_bf16(acc[0][2 * ng + 0], a[0], r0, r2);
                mma_bf16(acc[0][2 * ng + 1], a[0], r1, r3);
                mma_bf16(acc[1][2 * ng + 0], a[1], r0, r2);
                mma_bf16(acc[1][2 * ng + 1], a[1], r1, r3);
            }
        }
        __syncthreads();
    }

    const int trow = lid >> 2;
    const int tcol = (lid & 3) * 2;
#pragma unroll
    for (int mt = 0; mt < 2; mt++) {
        int r0 = bm + wm * 32 + mt * 16 + trow;
#pragma unroll
        for (int nt = 0; nt < 8; nt++) {
            int cc = bn + wn * 64 + nt * 8 + tcol;
            float2 bv = *(const float2*)(bias + cc);
            float o00 = acc[mt][nt][0] + bv.x;
            float o01 = acc[mt][nt][1] + bv.y;
            float o10 = acc[mt][nt][2] + bv.x;
            float o11 = acc[mt][nt][3] + bv.y;
            if (C) {
                *(float2*)(C + (size_t)r0 * DD + cc) = make_float2(o00, o01);
                *(float2*)(C + (size_t)(r0 + 8) * DD + cc) = make_float2(o10, o11);
            }
            if (Cb) {
                *(__nv_bfloat162*)(Cb + (size_t)r0 * DD + cc) =
                    __nv_bfloat162(__float2bfloat16(o00), __float2bfloat16(o01));
                *(__nv_bfloat162*)(Cb + (size_t)(r0 + 8) * DD + cc) =
                    __nv_bfloat162(__float2bfloat16(o10), __float2bfloat16(o11));
            }
        }
    }
}

// ---------------------------------------------------------------------------
// z_mma: HMMA Z row-sums.
// Grid: (SS/128 i-tiles, BB*HH). 256 threads = 8 warps; warp w owns rows
// [i0+16w, i0+16w+16). Q A-frags resident in registers; K streamed in
// 64-row double-buffered cp.async chunks from the diagonal block onward.
//   Z_i = i + sum_{r>=i} exp(s_ir/sqrt(D)),  E_i = exp(s_ii/sqrt(D))
// ---------------------------------------------------------------------------
#define ZSMEM (128 * ZRS + 2 * 64 * ZRS)   // 34816 + 34816 = 69632

__global__ __launch_bounds__(256) void z_mma(
    const __nv_bfloat16* __restrict__ Qb, const __nv_bfloat16* __restrict__ Kb)
{
    extern __shared__ __align__(16) unsigned char zsm[];
    unsigned char* Qs = zsm;                    // 128 x 272B
    unsigned char* Ks[2] = { zsm + 128 * ZRS, zsm + 128 * ZRS + 64 * ZRS };

    const int tid = threadIdx.x;
    const int lid = tid & 31;
    const int w = tid >> 5;
    const int bh = blockIdx.y;
    const int b = bh >> 4;
    const int h = bh & 15;
    const int i0 = blockIdx.x * 128;
    const float scale = 0.022097086912079612f;   // 1/sqrt(2048)

    const __nv_bfloat16* Qg = Qb + ((size_t)b * SS + i0) * DD + h * HDIM;
    const __nv_bfloat16* Kg = Kb + (size_t)b * SS * DD + h * HDIM;

    // load Q tile (128 rows x 256B)
    for (int i = tid; i < 128 * 16; i += 256) {
        int r = i >> 4, seg = i & 15;
        cp16(smem_u32(Qs + r * ZRS + seg * 16), Qg + (size_t)r * DD + seg * 8);
    }
    asm volatile("cp.async.commit_group;" ::: "memory");

    // load K chunk 0 (r0 = i0)
    for (int i = tid; i < 64 * 16; i += 256) {
        int r = i >> 4, seg = i & 15;
        cp16(smem_u32(Ks[0] + r * ZRS + seg * 16), Kg + (size_t)(i0 + r) * DD + seg * 8);
    }
    asm volatile("cp.async.commit_group;" ::: "memory");
    asm volatile("cp.async.wait_group 0;" ::: "memory");
    __syncthreads();

    // resident A fragments: 8 k-steps x 4 regs
    const int rowsel = (lid & 7) + ((lid >> 3) & 1) * 8;
    const int kbsel = (lid >> 4) * 16;
    uint32_t afr[8][4];
    {
        uint32_t aAddr = smem_u32(Qs) + (w * 16 + rowsel) * ZRS + kbsel;
#pragma unroll
        for (int ks = 0; ks < 8; ks++)
            ldsm4(afr[ks][0], afr[ks][1], afr[ks][2], afr[ks][3], aAddr + ks * 32);
    }

    const int gi0 = i0 + w * 16 + (lid >> 2);    // rows gi0 and gi0+8
    float z0 = 0.0f, z1 = 0.0f;
    float* Ep = g_E + (size_t)bh * SS;

    const int nch = (SS - i0) >> 6;
    for (int c = 0; c < nch; c++) {
        if (c + 1 < nch) {
            int r1 = i0 + (c + 1) * 64;
            unsigned char* kb = Ks[(c + 1) & 1];
            for (int i = tid; i < 64 * 16; i += 256) {
                int r = i >> 4, seg = i & 15;
                cp16(smem_u32(kb + r * ZRS + seg * 16),
                     Kg + (size_t)(r1 + r) * DD + seg * 8);
            }
            asm volatile("cp.async.commit_group;" ::: "memory");
            asm volatile("cp.async.wait_group 1;" ::: "memory");
        } else {
            asm volatile("cp.async.wait_group 0;" ::: "memory");
        }
        __syncthreads();

        const int r0 = i0 + c * 64;
        // skip chunks entirely below this warp's diagonal rows
        if (r0 + 64 > i0 + w * 16) {
            float sacc[8][4];
#pragma unroll
            for (int nt = 0; nt < 8; nt++)
#pragma unroll
                for (int q = 0; q < 4; q++) sacc[nt][q] = 0.0f;

            uint32_t bAddr = smem_u32(Ks[c & 1]) + rowsel * ZRS + kbsel;
#pragma unroll
            for (int ks = 0; ks < 8; ks++) {
#pragma unroll
                for (int ng = 0; ng < 4; ng++) {
                    uint32_t r0r, r1r, r2r, r3r;
                    ldsm4(r0r, r1r, r2r, r3r, bAddr + ng * 16 * ZRS + ks * 32);
                    mma_bf16(sacc[2 * ng + 0], afr[ks], r0r, r2r);
                    mma_bf16(sacc[2 * ng + 1], afr[ks], r1r, r3r);
                }
            }

            const bool needmask = (r0 < i0 + w * 16 + 16);
            const int grb = r0 + 2 * (lid & 3);
#pragma unroll
            for (int nt = 0; nt < 8; nt++) {
                int gr = grb + nt * 8;
                if (!needmask) {
                    z0 += __expf(sacc[nt][0] * scale) + __expf(sacc[nt][1] * scale);
                    z1 += __expf(sacc[nt][2] * scale) + __expf(sacc[nt][3] * scale);
                } else {
                    if (gr >= gi0) {
                        float e = __expf(sacc[nt][0] * scale);
                        z0 += e;
                        if (gr == gi0) Ep[gi0] = e;
                    }
                    if (gr + 1 >= gi0) {
                        float e = __expf(sacc[nt][1] * scale);
                        z0 += e;
                        if (gr + 1 == gi0) Ep[gi0] = e;
                    }
                    if (gr >= gi0 + 8) {
                        float e = __expf(sacc[nt][2] * scale);
                        z1 += e;
                        if (gr == gi0 + 8) Ep[gi0 + 8] = e;
                    }
                    if (gr + 1 >= gi0 + 8) {
                        float e = __expf(sacc[nt][3] * scale);
                        z1 += e;
                        if (gr + 1 == gi0 + 8) Ep[gi0 + 8] = e;
                    }
                }
            }
        }
        __syncthreads();
    }

    // reduce over the 4 lanes sharing each row
    z0 += __shfl_xor_sync(0xffffffffu, z0, 1);
    z0 += __shfl_xor_sync(0xffffffffu, z0, 2);
    z1 += __shfl_xor_sync(0xffffffffu, z1, 1);
    z1 += __shfl_xor_sync(0xffffffffu, z1, 2);
    if ((lid & 3) == 0) {
        g_Z[(size_t)bh * SS + gi0] = (float)gi0 + z0;
        g_Z[(size_t)bh * SS + gi0 + 8] = (float)(gi0 + 8) + z1;
    }
}

// ---------------------------------------------------------------------------
// Prefix-sum of V + apply (writes bf16 hi/lo split of attn directly)
// ---------------------------------------------------------------------------
__global__ void vchunk_kernel(const float* __restrict__ V)
{
    const int bh = blockIdx.x, ch = blockIdx.y, d = threadIdx.x;
    const int b = bh >> 4, h = bh & 15;
    const float* vp = V + ((size_t)b * SS + ch * 128) * DD + h * HDIM + d;
    float sum = 0.0f;
#pragma unroll 8
    for (int i = 0; i < 128; i++) sum += vp[(size_t)i * DD];
    g_cs[((size_t)bh * NCH + ch) * HDIM + d] = sum;
}

__global__ void vprefix_kernel()
{
    const int bh = blockIdx.x, d = threadIdx.x;
    float run = 0.0f;
    for (int ch = 0; ch < NCH; ch++) {
        size_t idx = ((size_t)bh * NCH + ch) * HDIM + d;
        float t = g_cs[idx];
        g_cs[idx] = run;
        run += t;
    }
}

__global__ void scan_apply_kernel(const float* __restrict__ V,
                                  __nv_bfloat16* __restrict__ Ah,
                                  __nv_bfloat16* __restrict__ Al)
{
    const int bh = blockIdx.x, ch = blockIdx.y, d = threadIdx.x;
    const int b = bh >> 4, h = bh & 15;
    float run = g_cs[((size_t)bh * NCH + ch) * HDIM + d];
    const size_t base = ((size_t)b * SS + ch * 128) * DD + h * HDIM + d;
    const float* vp = V + base;
    const float* Ep = g_E + (size_t)bh * SS + ch * 128;
    const float* Zp = g_Z + (size_t)bh * SS + ch * 128;
#pragma unroll 4
    for (int i = 0; i < 128; i++) {
        float vv = vp[(size_t)i * DD];
        float rcp = __fdividef(1.0f, Zp[i]);
        float val = (run + Ep[i] * vv) * rcp;
        __nv_bfloat16 hh = __float2bfloat16(val);
        Ah[base + (size_t)i * DD] = hh;
        Al[base + (size_t)i * DD] = __float2bfloat16(val - __bfloat162float(hh));
        run += vv;
    }
}

// ---------------------------------------------------------------------------
// Launch
// ---------------------------------------------------------------------------
extern "C" void kernel_launch(void* const* d_in, const int* in_sizes, int n_in,
                              void* d_out, int out_size)
{
    const float* x   = (const float*)d_in[0];
    const float* wq  = (const float*)d_in[1];
    const float* bq  = (const float*)d_in[2];
    const float* wk  = (const float*)d_in[3];
    const float* bk  = (const float*)d_in[4];
    const float* wv  = (const float*)d_in[5];
    const float* bv  = (const float*)d_in[6];
    const float* wo  = (const float*)d_in[7];
    const float* bo  = (const float*)d_in[8];
    float* out = (float*)d_out;

    void *pv, *pqb, *pkb;
    cudaGetSymbolAddress(&pv, g_v);
    cudaGetSymbolAddress(&pqb, g_qb);
    cudaGetSymbolAddress(&pkb, g_kb);
    float* v = (float*)pv;
    __nv_bfloat16* qb = (__nv_bfloat16*)pqb;
    __nv_bfloat16* kb = (__nv_bfloat16*)pkb;

    void *pxh, *pxl, *pah, *pal, *pwqh, *pwkh, *pwvh, *pwvl, *pwoh, *pwol;
    cudaGetSymbolAddress(&pxh, g_xh);   cudaGetSymbolAddress(&pxl, g_xl);
    cudaGetSymbolAddress(&pah, g_ah);   cudaGetSymbolAddress(&pal, g_al);
    cudaGetSymbolAddress(&pwqh, g_wqh); cudaGetSymbolAddress(&pwkh, g_wkh);
    cudaGetSymbolAddress(&pwvh, g_wvh); cudaGetSymbolAddress(&pwvl, g_wvl);
    cudaGetSymbolAddress(&pwoh, g_woh); cudaGetSymbolAddress(&pwol, g_wol);

    __nv_bfloat16* xh = (__nv_bfloat16*)pxh;
    __nv_bfloat16* xl = (__nv_bfloat16*)pxl;
    __nv_bfloat16* ah = (__nv_bfloat16*)pah;
    __nv_bfloat16* al = (__nv_bfloat16*)pal;
    __nv_bfloat16* wqh = (__nv_bfloat16*)pwqh;
    __nv_bfloat16* wkh = (__nv_bfloat16*)pwkh;
    __nv_bfloat16* wvh = (__nv_bfloat16*)pwvh;
    __nv_bfloat16* wvl = (__nv_bfloat16*)pwvl;
    __nv_bfloat16* woh = (__nv_bfloat16*)pwoh;
    __nv_bfloat16* wol = (__nv_bfloat16*)pwol;

    cudaFuncSetAttribute(z_mma, cudaFuncAttributeMaxDynamicSharedMemorySize, ZSMEM);

    const int nTok = NTOK * DD;   // 8.4M
    const int nW   = DD * DD;     // 4.2M

    split_kernel<<<nTok / 1024, 256>>>(x, xh, xl, nTok);
    tobf16_kernel<<<nW / 1024, 256>>>(wq, wqh, nW);
    tobf16_kernel<<<nW / 1024, 256>>>(wk, wkh, nW);
    split_kernel<<<nW / 1024, 256>>>(wv, wvh, wvl, nW);
    split_kernel<<<nW / 1024, 256>>>(wo, woh, wol, nW);

    dim3 gGemm(DD / 128, NTOK / 128);   // (16, 32)
    // Q, K: single bf16 product -> bf16 output only
    gemm_mma<<<gGemm, 256>>>(xh, wqh, xh, wqh, xh, wqh, 1, bq, nullptr, qb);
    gemm_mma<<<gGemm, 256>>>(xh, wkh, xh, wkh, xh, wkh, 1, bk, nullptr, kb);
    // V: 3-way split -> fp32
    gemm_mma<<<gGemm, 256>>>(xh, wvh, xh, wvl, xl, wvh, 3, bv, v, nullptr);

    dim3 gZ(SS / 128, BB * HH);         // (16, 32)
    z_mma<<<gZ, 256, ZSMEM>>>(qb, kb);

    dim3 gScan(BB * HH, NCH);
    vchunk_kernel<<<gScan, HDIM>>>(v);
    vprefix_kernel<<<BB * HH, HDIM>>>();
    scan_apply_kernel<<<gScan, HDIM>>>(v, ah, al);

    // O-projection: 3-way split -> fp32 out
    gemm_mma<<<gGemm, 256>>>(ah, woh, ah, wol, al, woh, 3, bo, out, nullptr);
}

// round 8
// speedup vs baseline: 3.9485x; 1.1283x over previous
#include <cuda_runtime.h>
#include <cuda_bf16.h>
#include <math.h>
#include <stdint.h>

// ---------------------------------------------------------------------------
// MultiHeadSelfAttention, B=2, S=2048, D=2048, H=16, HD=128
//
//   attn_i = ( sum_{j<i} v_j + exp(s_ii) * v_i ) / Z_i
//   Z_i    = i + sum_{r>=i} exp( (q_i . k_r) / sqrt(D) )
//
// Round 6: GEMM rebuilt for smem-crossbar efficiency: 64x64 warp tile,
// BK=64, 4 warps, 2 CTAs/SM. (Old: 32x64 tile was crossbar-bound.)
// ---------------------------------------------------------------------------

#define BB 2
#define SS 2048
#define DD 2048
#define HH 16
#define HDIM 128
#define NTOK (BB * SS)         // 4096
#define NCH 16
#define RS2 144                // gemm smem row stride (128B data + 16B pad)
#define STG (128 * RS2)        // one tile = 18432 B
#define GSM2 (4 * STG)         // 2 stages x (A + B) = 73728 B
#define ZRS 272                // z smem row stride (256B data + 16B pad)

// fp32 scratch
__device__ float g_v[(size_t)NTOK * DD];
__device__ float g_Z[BB * HH * SS];
__device__ float g_E[BB * HH * SS];
__device__ float g_cs[BB * HH * NCH * HDIM];

// bf16 scratch
__device__ __nv_bfloat16 g_xh[(size_t)NTOK * DD];
__device__ __nv_bfloat16 g_xl[(size_t)NTOK * DD];
__device__ __nv_bfloat16 g_qb[(size_t)NTOK * DD];
__device__ __nv_bfloat16 g_kb[(size_t)NTOK * DD];
__device__ __nv_bfloat16 g_ah[(size_t)NTOK * DD];
__device__ __nv_bfloat16 g_al[(size_t)NTOK * DD];
__device__ __nv_bfloat16 g_wqh[(size_t)DD * DD];
__device__ __nv_bfloat16 g_wkh[(size_t)DD * DD];
__device__ __nv_bfloat16 g_wvh[(size_t)DD * DD];
__device__ __nv_bfloat16 g_wvl[(size_t)DD * DD];
__device__ __nv_bfloat16 g_woh[(size_t)DD * DD];
__device__ __nv_bfloat16 g_wol[(size_t)DD * DD];

// ---------------------------------------------------------------------------
// Helpers (base compute_103 ISA only)
// ---------------------------------------------------------------------------
__device__ __forceinline__ uint32_t smem_u32(const void* p) {
    return (uint32_t)__cvta_generic_to_shared(p);
}

__device__ __forceinline__ void cp16(uint32_t dst, const void* src) {
    asm volatile("cp.async.cg.shared.global [%0], [%1], 16;" :: "r"(dst), "l"(src));
}

__device__ __forceinline__ void ldsm4(uint32_t& r0, uint32_t& r1, uint32_t& r2,
                                      uint32_t& r3, uint32_t addr) {
    asm volatile("ldmatrix.sync.aligned.m8n8.x4.shared.b16 {%0,%1,%2,%3}, [%4];"
                 : "=r"(r0), "=r"(r1), "=r"(r2), "=r"(r3) : "r"(addr));
}

__device__ __forceinline__ void mma_bf16(float* c, const uint32_t* a,
                                         uint32_t b0, uint32_t b1) {
    asm volatile("mma.sync.aligned.m16n8k16.row.col.f32.bf16.bf16.f32 "
                 "{%0,%1,%2,%3}, {%4,%5,%6,%7}, {%8,%9}, {%0,%1,%2,%3};"
                 : "+f"(c[0]), "+f"(c[1]), "+f"(c[2]), "+f"(c[3])
                 : "r"(a[0]), "r"(a[1]), "r"(a[2]), "r"(a[3]), "r"(b0), "r"(b1));
}

// ---------------------------------------------------------------------------
// fp32 -> bf16 conversions
// ---------------------------------------------------------------------------
__global__ __launch_bounds__(256) void split_kernel(
    const float* __restrict__ in, __nv_bfloat16* __restrict__ hi,
    __nv_bfloat16* __restrict__ lo, int n)
{
    int i = (blockIdx.x * 256 + threadIdx.x) * 4;
    if (i >= n) return;
    float4 v = *(const float4*)(in + i);
    __nv_bfloat16 h0 = __float2bfloat16(v.x);
    __nv_bfloat16 h1 = __float2bfloat16(v.y);
    __nv_bfloat16 h2 = __float2bfloat16(v.z);
    __nv_bfloat16 h3 = __float2bfloat16(v.w);
    __nv_bfloat16 l0 = __float2bfloat16(v.x - __bfloat162float(h0));
    __nv_bfloat16 l1 = __float2bfloat16(v.y - __bfloat162float(h1));
    __nv_bfloat16 l2 = __float2bfloat16(v.z - __bfloat162float(h2));
    __nv_bfloat16 l3 = __float2bfloat16(v.w - __bfloat162float(h3));
    __nv_bfloat162* hp = reinterpret_cast<__nv_bfloat162*>(hi + i);
    __nv_bfloat162* lp = reinterpret_cast<__nv_bfloat162*>(lo + i);
    hp[0] = __nv_bfloat162(h0, h1);
    hp[1] = __nv_bfloat162(h2, h3);
    lp[0] = __nv_bfloat162(l0, l1);
    lp[1] = __nv_bfloat162(l2, l3);
}

__global__ __launch_bounds__(256) void tobf16_kernel(
    const float* __restrict__ in, __nv_bfloat16* __restrict__ out, int n)
{
    int i = (blockIdx.x * 256 + threadIdx.x) * 4;
    if (i >= n) return;
    float4 v = *(const float4*)(in + i);
    __nv_bfloat162* op = reinterpret_cast<__nv_bfloat162*>(out + i);
    op[0] = __nv_bfloat162(__float2bfloat16(v.x), __float2bfloat16(v.y));
    op[1] = __nv_bfloat162(__float2bfloat16(v.z), __float2bfloat16(v.w));
}

// ---------------------------------------------------------------------------
// bf16 mma.sync GEMM: C[m,n] = sum_p sum_k Ap[m,k]*Bp[n,k]  (+ bias[n])
// CTA tile 128x128, BK=64, 128 threads (4 warps as 2x2), warp tile 64x64.
// Double-buffered cp.async; smem rows padded to 144B (conflict-free ldsm).
// ---------------------------------------------------------------------------
__device__ __forceinline__ void gemm_load_chunk(
    const __nv_bfloat16* __restrict__ A, const __nv_bfloat16* __restrict__ B,
    int bm, int bn, int k0, unsigned char* sA, unsigned char* sB, int tid)
{
#pragma unroll
    for (int l = 0; l < 8; l++) {
        int i = tid + l * 128;          // 1024 x 16B per tile
        int r = i >> 3;
        int seg = i & 7;
        cp16(smem_u32(sA + r * RS2 + seg * 16),
             A + (size_t)(bm + r) * DD + k0 + seg * 8);
        cp16(smem_u32(sB + r * RS2 + seg * 16),
             B + (size_t)(bn + r) * DD + k0 + seg * 8);
    }
    asm volatile("cp.async.commit_group;" ::: "memory");
}

__global__ __launch_bounds__(128) void gemm_mma(
    const __nv_bfloat16* __restrict__ A0, const __nv_bfloat16* __restrict__ B0,
    const __nv_bfloat16* __restrict__ A1, const __nv_bfloat16* __restrict__ B1,
    const __nv_bfloat16* __restrict__ A2, const __nv_bfloat16* __restrict__ B2,
    int nprod, const float* __restrict__ bias, float* __restrict__ C,
    __nv_bfloat16* __restrict__ Cb)
{
    extern __shared__ __align__(16) unsigned char gsm[];
    unsigned char* sA[2] = { gsm, gsm + 2 * STG };
    unsigned char* sB[2] = { gsm + STG, gsm + 3 * STG };

    const int tid = threadIdx.x;
    const int lid = tid & 31;
    const int wid = tid >> 5;
    const int wm = wid >> 1;          // 0..1
    const int wn = wid & 1;           // 0..1
    const int bn = blockIdx.x * 128;
    const int bm = blockIdx.y * 128;

    const __nv_bfloat16* Ap[3] = {A0, A1, A2};
    const __nv_bfloat16* Bp[3] = {B0, B1, B2};
    const int nch = nprod << 5;       // 32 chunks of BK=64 per product

    float acc[4][8][4];
#pragma unroll
    for (int i = 0; i < 4; i++)
#pragma unroll
        for (int j = 0; j < 8; j++)
#pragma unroll
            for (int q = 0; q < 4; q++) acc[i][j][q] = 0.0f;

    const int rowsel = (lid & 7) + ((lid >> 3) & 1) * 8;
    const int kbsel = (lid >> 4) * 16;

    gemm_load_chunk(Ap[0], Bp[0], bm, bn, 0, sA[0], sB[0], tid);

    for (int c = 0; c < nch; c++) {
        if (c + 1 < nch) {
            int p = (c + 1) >> 5;
            gemm_load_chunk(Ap[p], Bp[p], bm, bn, ((c + 1) & 31) << 6,
                            sA[(c + 1) & 1], sB[(c + 1) & 1], tid);
            asm volatile("cp.async.wait_group 1;" ::: "memory");
        } else {
            asm volatile("cp.async.wait_group 0;" ::: "memory");
        }
        __syncthreads();

        const int buf = c & 1;
        uint32_t aBase = smem_u32(sA[buf]) + (wm * 64 + rowsel) * RS2 + kbsel;
        uint32_t bBase = smem_u32(sB[buf]) + (wn * 64 + rowsel) * RS2 + kbsel;

#pragma unroll
        for (int ks = 0; ks < 4; ks++) {
            uint32_t a[4][4];
#pragma unroll
            for (int mf = 0; mf < 4; mf++)
                ldsm4(a[mf][0], a[mf][1], a[mf][2], a[mf][3],
                      aBase + mf * 16 * RS2 + ks * 32);
#pragma unroll
            for (int ng = 0; ng < 4; ng++) {
                uint32_t r0, r1, r2, r3;
                ldsm4(r0, r1, r2, r3, bBase + ng * 16 * RS2 + ks * 32);
#pragma unroll
                for (int mf = 0; mf < 4; mf++) {
                    mma_bf16(acc[mf][2 * ng + 0], a[mf], r0, r2);
                    mma_bf16(acc[mf][2 * ng + 1], a[mf], r1, r3);
                }
            }
        }
        __syncthreads();
    }

    const int trow = lid >> 2;
    const int tcol = (lid & 3) * 2;
#pragma unroll
    for (int mf = 0; mf < 4; mf++) {
        int r0 = bm + wm * 64 + mf * 16 + trow;
#pragma unroll
        for (int nt = 0; nt < 8; nt++) {
            int cc = bn + wn * 64 + nt * 8 + tcol;
            float2 bv = *(const float2*)(bias + cc);
            float o00 = acc[mf][nt][0] + bv.x;
            float o01 = acc[mf][nt][1] + bv.y;
            float o10 = acc[mf][nt][2] + bv.x;
            float o11 = acc[mf][nt][3] + bv.y;
            if (C) {
                *(float2*)(C + (size_t)r0 * DD + cc) = make_float2(o00, o01);
                *(float2*)(C + (size_t)(r0 + 8) * DD + cc) = make_float2(o10, o11);
            }
            if (Cb) {
                *(__nv_bfloat162*)(Cb + (size_t)r0 * DD + cc) =
                    __nv_bfloat162(__float2bfloat16(o00), __float2bfloat16(o01));
                *(__nv_bfloat162*)(Cb + (size_t)(r0 + 8) * DD + cc) =
                    __nv_bfloat162(__float2bfloat16(o10), __float2bfloat16(o11));
            }
        }
    }
}

// ---------------------------------------------------------------------------
// z_mma: HMMA Z row-sums.
// Grid: (SS/128 i-tiles, BB*HH). 256 threads = 8 warps; warp w owns rows
// [i0+16w, i0+16w+16). Q A-frags resident in registers; K streamed in
// 64-row double-buffered cp.async chunks from the diagonal block onward.
// ---------------------------------------------------------------------------
#define ZSMEM (128 * ZRS + 2 * 64 * ZRS)   // 69632

__global__ __launch_bounds__(256) void z_mma(
    const __nv_bfloat16* __restrict__ Qb, const __nv_bfloat16* __restrict__ Kb)
{
    extern __shared__ __align__(16) unsigned char zsm[];
    unsigned char* Qs = zsm;                    // 128 x 272B
    unsigned char* Ks[2] = { zsm + 128 * ZRS, zsm + 128 * ZRS + 64 * ZRS };

    const int tid = threadIdx.x;
    const int lid = tid & 31;
    const int w = tid >> 5;
    const int bh = blockIdx.y;
    const int b = bh >> 4;
    const int h = bh & 15;
    const int i0 = blockIdx.x * 128;
    const float scale = 0.022097086912079612f;   // 1/sqrt(2048)

    const __nv_bfloat16* Qg = Qb + ((size_t)b * SS + i0) * DD + h * HDIM;
    const __nv_bfloat16* Kg = Kb + (size_t)b * SS * DD + h * HDIM;

    for (int i = tid; i < 128 * 16; i += 256) {
        int r = i >> 4, seg = i & 15;
        cp16(smem_u32(Qs + r * ZRS + seg * 16), Qg + (size_t)r * DD + seg * 8);
    }
    asm volatile("cp.async.commit_group;" ::: "memory");

    for (int i = tid; i < 64 * 16; i += 256) {
        int r = i >> 4, seg = i & 15;
        cp16(smem_u32(Ks[0] + r * ZRS + seg * 16), Kg + (size_t)(i0 + r) * DD + seg * 8);
    }
    asm volatile("cp.async.commit_group;" ::: "memory");
    asm volatile("cp.async.wait_group 0;" ::: "memory");
    __syncthreads();

    const int rowsel = (lid & 7) + ((lid >> 3) & 1) * 8;
    const int kbsel = (lid >> 4) * 16;
    uint32_t afr[8][4];
    {
        uint32_t aAddr = smem_u32(Qs) + (w * 16 + rowsel) * ZRS + kbsel;
#pragma unroll
        for (int ks = 0; ks < 8; ks++)
            ldsm4(afr[ks][0], afr[ks][1], afr[ks][2], afr[ks][3], aAddr + ks * 32);
    }

    const int gi0 = i0 + w * 16 + (lid >> 2);    // rows gi0 and gi0+8
    float z0 = 0.0f, z1 = 0.0f;
    float* Ep = g_E + (size_t)bh * SS;

    const int nch = (SS - i0) >> 6;
    for (int c = 0; c < nch; c++) {
        if (c + 1 < nch) {
            int r1 = i0 + (c + 1) * 64;
            unsigned char* kb = Ks[(c + 1) & 1];
            for (int i = tid; i < 64 * 16; i += 256) {
                int r = i >> 4, seg = i & 15;
                cp16(smem_u32(kb + r * ZRS + seg * 16),
                     Kg + (size_t)(r1 + r) * DD + seg * 8);
            }
            asm volatile("cp.async.commit_group;" ::: "memory");
            asm volatile("cp.async.wait_group 1;" ::: "memory");
        } else {
            asm volatile("cp.async.wait_group 0;" ::: "memory");
        }
        __syncthreads();

        const int r0 = i0 + c * 64;
        if (r0 + 64 > i0 + w * 16) {
            float sacc[8][4];
#pragma unroll
            for (int nt = 0; nt < 8; nt++)
#pragma unroll
                for (int q = 0; q < 4; q++) sacc[nt][q] = 0.0f;

            uint32_t bAddr = smem_u32(Ks[c & 1]) + rowsel * ZRS + kbsel;
#pragma unroll
            for (int ks = 0; ks < 8; ks++) {
#pragma unroll
                for (int ng = 0; ng < 4; ng++) {
                    uint32_t r0r, r1r, r2r, r3r;
                    ldsm4(r0r, r1r, r2r, r3r, bAddr + ng * 16 * ZRS + ks * 32);
                    mma_bf16(sacc[2 * ng + 0], afr[ks], r0r, r2r);
                    mma_bf16(sacc[2 * ng + 1], afr[ks], r1r, r3r);
                }
            }

            const bool needmask = (r0 < i0 + w * 16 + 16);
            const int grb = r0 + 2 * (lid & 3);
#pragma unroll
            for (int nt = 0; nt < 8; nt++) {
                int gr = grb + nt * 8;
                if (!needmask) {
                    z0 += __expf(sacc[nt][0] * scale) + __expf(sacc[nt][1] * scale);
                    z1 += __expf(sacc[nt][2] * scale) + __expf(sacc[nt][3] * scale);
                } else {
                    if (gr >= gi0) {
                        float e = __expf(sacc[nt][0] * scale);
                        z0 += e;
                        if (gr == gi0) Ep[gi0] = e;
                    }
                    if (gr + 1 >= gi0) {
                        float e = __expf(sacc[nt][1] * scale);
                        z0 += e;
                        if (gr + 1 == gi0) Ep[gi0] = e;
                    }
                    if (gr >= gi0 + 8) {
                        float e = __expf(sacc[nt][2] * scale);
                        z1 += e;
                        if (gr == gi0 + 8) Ep[gi0 + 8] = e;
                    }
                    if (gr + 1 >= gi0 + 8) {
                        float e = __expf(sacc[nt][3] * scale);
                        z1 += e;
                        if (gr + 1 == gi0 + 8) Ep[gi0 + 8] = e;
                    }
                }
            }
        }
        __syncthreads();
    }

    z0 += __shfl_xor_sync(0xffffffffu, z0, 1);
    z0 += __shfl_xor_sync(0xffffffffu, z0, 2);
    z1 += __shfl_xor_sync(0xffffffffu, z1, 1);
    z1 += __shfl_xor_sync(0xffffffffu, z1, 2);
    if ((lid & 3) == 0) {
        g_Z[(size_t)bh * SS + gi0] = (float)gi0 + z0;
        g_Z[(size_t)bh * SS + gi0 + 8] = (float)(gi0 + 8) + z1;
    }
}

// ---------------------------------------------------------------------------
// Prefix-sum of V + apply (writes bf16 hi/lo split of attn directly)
// ---------------------------------------------------------------------------
__global__ void vchunk_kernel(const float* __restrict__ V)
{
    const int bh = blockIdx.x, ch = blockIdx.y, d = threadIdx.x;
    const int b = bh >> 4, h = bh & 15;
    const float* vp = V + ((size_t)b * SS + ch * 128) * DD + h * HDIM + d;
    float sum = 0.0f;
#pragma unroll 8
    for (int i = 0; i < 128; i++) sum += vp[(size_t)i * DD];
    g_cs[((size_t)bh * NCH + ch) * HDIM + d] = sum;
}

__global__ void vprefix_kernel()
{
    const int bh = blockIdx.x, d = threadIdx.x;
    float run = 0.0f;
    for (int ch = 0; ch < NCH; ch++) {
        size_t idx = ((size_t)bh * NCH + ch) * HDIM + d;
        float t = g_cs[idx];
        g_cs[idx] = run;
        run += t;
    }
}

__global__ void scan_apply_kernel(const float* __restrict__ V,
                                  __nv_bfloat16* __restrict__ Ah,
                                  __nv_bfloat16* __restrict__ Al)
{
    const int bh = blockIdx.x, ch = blockIdx.y, d = threadIdx.x;
    const int b = bh >> 4, h = bh & 15;
    float run = g_cs[((size_t)bh * NCH + ch) * HDIM + d];
    const size_t base = ((size_t)b * SS + ch * 128) * DD + h * HDIM + d;
    const float* vp = V + base;
    const float* Ep = g_E + (size_t)bh * SS + ch * 128;
    const float* Zp = g_Z + (size_t)bh * SS + ch * 128;
#pragma unroll 4
    for (int i = 0; i < 128; i++) {
        float vv = vp[(size_t)i * DD];
        float rcp = __fdividef(1.0f, Zp[i]);
        float val = (run + Ep[i] * vv) * rcp;
        __nv_bfloat16 hh = __float2bfloat16(val);
        Ah[base + (size_t)i * DD] = hh;
        Al[base + (size_t)i * DD] = __float2bfloat16(val - __bfloat162float(hh));
        run += vv;
    }
}

// ---------------------------------------------------------------------------
// Launch
// ---------------------------------------------------------------------------
extern "C" void kernel_launch(void* const* d_in, const int* in_sizes, int n_in,
                              void* d_out, int out_size)
{
    const float* x   = (const float*)d_in[0];
    const float* wq  = (const float*)d_in[1];
    const float* bq  = (const float*)d_in[2];
    const float* wk  = (const float*)d_in[3];
    const float* bk  = (const float*)d_in[4];
    const float* wv  = (const float*)d_in[5];
    const float* bv  = (const float*)d_in[6];
    const float* wo  = (const float*)d_in[7];
    const float* bo  = (const float*)d_in[8];
    float* out = (float*)d_out;

    void *pv, *pqb, *pkb;
    cudaGetSymbolAddress(&pv, g_v);
    cudaGetSymbolAddress(&pqb, g_qb);
    cudaGetSymbolAddress(&pkb, g_kb);
    float* v = (float*)pv;
    __nv_bfloat16* qb = (__nv_bfloat16*)pqb;
    __nv_bfloat16* kb = (__nv_bfloat16*)pkb;

    void *pxh, *pxl, *pah, *pal, *pwqh, *pwkh, *pwvh, *pwvl, *pwoh, *pwol;
    cudaGetSymbolAddress(&pxh, g_xh);   cudaGetSymbolAddress(&pxl, g_xl);
    cudaGetSymbolAddress(&pah, g_ah);   cudaGetSymbolAddress(&pal, g_al);
    cudaGetSymbolAddress(&pwqh, g_wqh); cudaGetSymbolAddress(&pwkh, g_wkh);
    cudaGetSymbolAddress(&pwvh, g_wvh); cudaGetSymbolAddress(&pwvl, g_wvl);
    cudaGetSymbolAddress(&pwoh, g_woh); cudaGetSymbolAddress(&pwol, g_wol);

    __nv_bfloat16* xh = (__nv_bfloat16*)pxh;
    __nv_bfloat16* xl = (__nv_bfloat16*)pxl;
    __nv_bfloat16* ah = (__nv_bfloat16*)pah;
    __nv_bfloat16* al = (__nv_bfloat16*)pal;
    __nv_bfloat16* wqh = (__nv_bfloat16*)pwqh;
    __nv_bfloat16* wkh = (__nv_bfloat16*)pwkh;
    __nv_bfloat16* wvh = (__nv_bfloat16*)pwvh;
    __nv_bfloat16* wvl = (__nv_bfloat16*)pwvl;
    __nv_bfloat16* woh = (__nv_bfloat16*)pwoh;
    __nv_bfloat16* wol = (__nv_bfloat16*)pwol;

    cudaFuncSetAttribute(gemm_mma, cudaFuncAttributeMaxDynamicSharedMemorySize, GSM2);
    cudaFuncSetAttribute(z_mma, cudaFuncAttributeMaxDynamicSharedMemorySize, ZSMEM);

    const int nTok = NTOK * DD;   // 8.4M
    const int nW   = DD * DD;     // 4.2M

    split_kernel<<<nTok / 1024, 256>>>(x, xh, xl, nTok);
    tobf16_kernel<<<nW / 1024, 256>>>(wq, wqh, nW);
    tobf16_kernel<<<nW / 1024, 256>>>(wk, wkh, nW);
    split_kernel<<<nW / 1024, 256>>>(wv, wvh, wvl, nW);
    split_kernel<<<nW / 1024, 256>>>(wo, woh, wol, nW);

    dim3 gGemm(DD / 128, NTOK / 128);   // (16, 32)
    // Q, K: single bf16 product -> bf16 output only
    gemm_mma<<<gGemm, 128, GSM2>>>(xh, wqh, xh, wqh, xh, wqh, 1, bq, nullptr, qb);
    gemm_mma<<<gGemm, 128, GSM2>>>(xh, wkh, xh, wkh, xh, wkh, 1, bk, nullptr, kb);
    // V: 3-way split -> fp32
    gemm_mma<<<gGemm, 128, GSM2>>>(xh, wvh, xh, wvl, xl, wvh, 3, bv, v, nullptr);

    dim3 gZ(SS / 128, BB * HH);         // (16, 32)
    z_mma<<<gZ, 256, ZSMEM>>>(qb, kb);

    dim3 gScan(BB * HH, NCH);
    vchunk_kernel<<<gScan, HDIM>>>(v);
    vprefix_kernel<<<BB * HH, HDIM>>>();
    scan_apply_kernel<<<gScan, HDIM>>>(v, ah, al);

    // O-projection: 3-way split -> fp32 out
    gemm_mma<<<gGemm, 128, GSM2>>>(ah, woh, ah, wol, al, woh, 3, bo, out, nullptr);
}